// round 16
// baseline (speedup 1.0000x reference)
#include <cuda_runtime.h>
#include <cuda_bf16.h>
#include <mma.h>
#include <cstdint>

using namespace nvcuda;

#define NN 50000
#define NNP 50048              // 391*128: padded rows for guard-free direct GEMM stores
#define NE 800000
#define EE (NE + NN)           // edges + self loops = 850000
#define HW 256
#define IN_FEAT 128
#define OUTF 40

// weight scratch offsets (tf32-rounded copies)
#define W1OFF 0
#define W2OFF 32768
#define W3OFF 98304
#define WM1OFF 163840
#define WTOT 229376

// ---------------- scratch ----------------
__device__ float g_h[NNP * HW];              // GEMM output (fp32)
__device__ __nv_bfloat16 g_hb[NN * HW];      // bf16 mirror of h for agg gathers
__device__ float g_feat[NN * HW];            // staged rounded x -> layer outputs
__device__ float g_wr[WTOT];                 // tf32-rounded weights
__device__ float g_srcl[NN * 4];
__device__ float g_dstl[NN * 4];
__device__ float g_amax[NN * 4];
__device__ int   g_src2[EE];
__device__ int   g_dst2[EE];
__device__ int   g_src_sorted[EE];
__device__ int   g_counts[NN];
__device__ int   g_fill[NN];
__device__ int   g_rowptr[NN + 1];
__device__ int   g_bsum[256];
__device__ int   g_is64;

// ---------------- cp.async helpers ----------------
__device__ __forceinline__ void cp16(void* dst_smem, const void* src) {
    uint32_t sa = (uint32_t)__cvta_generic_to_shared(dst_smem);
    asm volatile("cp.async.ca.shared.global [%0], [%1], 16;\n" :: "r"(sa), "l"(src));
}
__device__ __forceinline__ void cp_commit() {
    asm volatile("cp.async.commit_group;\n");
}
template <int N>
__device__ __forceinline__ void cp_wait() {
    asm volatile("cp.async.wait_group %0;\n" :: "n"(N));
}

// ---------------- dtype detection ----------------
__global__ void k_detect(const void* __restrict__ ei) {
    __shared__ int bad;
    if (threadIdx.x == 0) bad = 0;
    __syncthreads();
    const long long* p = (const long long*)ei;
    long long v = p[threadIdx.x];
    if (v < 0 || v >= (long long)NN) bad = 1;
    __syncthreads();
    if (threadIdx.x == 0) g_is64 = bad ? 0 : 1;
}

// ---------------- tf32 pre-rounding ----------------
__global__ void k_round_w(const float* __restrict__ W1, const float* __restrict__ W2,
                          const float* __restrict__ W3, const float* __restrict__ Wm1) {
    int i = blockIdx.x * blockDim.x + threadIdx.x;
    if (i >= WTOT) return;
    float v;
    if (i < W2OFF)       v = W1[i];
    else if (i < W3OFF)  v = W2[i - W2OFF];
    else if (i < WM1OFF) v = W3[i - W3OFF];
    else                 v = Wm1[i - WM1OFF];
    g_wr[i] = wmma::__float_to_tf32(v);
}

__global__ void k_round_x(const float* __restrict__ x, float* __restrict__ dst) {
    int i = blockIdx.x * blockDim.x + threadIdx.x;
    if (i >= NN * IN_FEAT) return;
    dst[i] = wmma::__float_to_tf32(x[i]);
}

// ---------------- h -> bf16 mirror ----------------
__global__ void k_h2b(const float* __restrict__ h, __nv_bfloat16* __restrict__ hb) {
    int i = blockIdx.x * blockDim.x + threadIdx.x;     // over NN*64 float4
    if (i >= NN * 64) return;
    float4 v = ((const float4*)h)[i];
    __nv_bfloat162 lo = __floats2bfloat162_rn(v.x, v.y);
    __nv_bfloat162 hi = __floats2bfloat162_rn(v.z, v.w);
    uint2 pack;
    pack.x = *(uint32_t*)&lo;
    pack.y = *(uint32_t*)&hi;
    ((uint2*)hb)[i] = pack;
}

// ---------------- GEMM v5 (validated R13): 256thr/8w, warp 64x32, cp.async --
#define BGM 128
#define BGN 128
#define BGK 32
#define PA 36
#define PB 132
#define ASZ (BGM * PA)
#define BSZ (BGK * PB)
#define G4_SMEM ((2 * ASZ + 2 * BSZ) * 4)   // 70656 bytes

__global__ __launch_bounds__(256, 2) void k_gemm4(
    const float* __restrict__ A, const float* __restrict__ B,
    float* __restrict__ C, int M, int K)
{
    extern __shared__ float smem[];
    float* As = smem;
    float* Bs = smem + 2 * ASZ;

    int tid = threadIdx.x;
    int warp = tid >> 5;
    int wm = warp >> 2;
    int wn = warp & 3;
    int row0 = blockIdx.y * BGM;
    int col0 = blockIdx.x * BGN;

    wmma::fragment<wmma::accumulator, 16, 16, 8, float> acc[4][2];
#pragma unroll
    for (int i = 0; i < 4; i++)
#pragma unroll
        for (int j = 0; j < 2; j++) wmma::fill_fragment(acc[i][j], 0.0f);

    const int T = K / BGK;

    auto issue = [&](int t, int buf) {
        int k0 = t * BGK;
        float* Ab = As + buf * ASZ;
        float* Bb = Bs + buf * BSZ;
#pragma unroll
        for (int i = 0; i < 4; i++) {
            int idx = tid + i * 256;
            int r = idx >> 3, c4 = (idx & 7) * 4;
            int gr = min(row0 + r, M - 1);
            cp16(Ab + r * PA + c4, A + (size_t)gr * K + k0 + c4);
        }
#pragma unroll
        for (int i = 0; i < 4; i++) {
            int idx = tid + i * 256;
            int r = idx >> 5, c4 = (idx & 31) * 4;
            cp16(Bb + r * PB + c4, B + (size_t)(k0 + r) * HW + col0 + c4);
        }
        cp_commit();
    };

    issue(0, 0);

    for (int t = 0; t < T; t++) {
        int buf = t & 1;
        if (t + 1 < T) { issue(t + 1, (t + 1) & 1); cp_wait<1>(); }
        else           { cp_wait<0>(); }
        __syncthreads();

        float* Ab = As + buf * ASZ;
        float* Bb = Bs + buf * BSZ;
#pragma unroll
        for (int kk = 0; kk < BGK; kk += 8) {
            wmma::fragment<wmma::matrix_a, 16, 16, 8, wmma::precision::tf32, wmma::row_major> a[4];
            wmma::fragment<wmma::matrix_b, 16, 16, 8, wmma::precision::tf32, wmma::row_major> b[2];
#pragma unroll
            for (int i = 0; i < 4; i++)
                wmma::load_matrix_sync(a[i], Ab + (wm * 64 + i * 16) * PA + kk, PA);
#pragma unroll
            for (int j = 0; j < 2; j++)
                wmma::load_matrix_sync(b[j], Bb + kk * PB + wn * 32 + j * 16, PB);
#pragma unroll
            for (int i = 0; i < 4; i++)
#pragma unroll
                for (int j = 0; j < 2; j++)
                    wmma::mma_sync(acc[i][j], a[i], b[j], acc[i][j]);
        }
        __syncthreads();
    }

#pragma unroll
    for (int i = 0; i < 4; i++)
#pragma unroll
        for (int j = 0; j < 2; j++) {
            int r = row0 + wm * 64 + i * 16;
            int c = col0 + wn * 32 + j * 16;
            wmma::store_matrix_sync(C + (size_t)r * HW + c, acc[i][j], HW,
                                    wmma::mem_row_major);
        }
}

// ---------------- CSR build ----------------
__global__ void k_zero_counts(int* counts, int n) {
    int i = blockIdx.x * blockDim.x + threadIdx.x;
    if (i < n) counts[i] = 0;
}

__global__ void k_build_edges(const void* __restrict__ ei,
                              int* __restrict__ src2, int* __restrict__ dst2,
                              int* __restrict__ counts) {
    int e = blockIdx.x * blockDim.x + threadIdx.x;
    if (e >= EE) return;
    int s, d;
    if (e < NE) {
        if (g_is64) {
            const long long* p = (const long long*)ei;
            s = (int)p[e]; d = (int)p[NE + e];
        } else {
            const int* p = (const int*)ei;
            s = p[e]; d = p[NE + e];
        }
        s = min(max(s, 0), NN - 1);
        d = min(max(d, 0), NN - 1);
    } else {
        s = d = e - NE;
    }
    src2[e] = s;
    dst2[e] = d;
    atomicAdd(&counts[d], 1);
}

#define SCAN_B 256
#define SCAN_NB ((NN + SCAN_B - 1) / SCAN_B)   // 196

__global__ void k_blocksum(const int* __restrict__ counts, int* __restrict__ bsum) {
    __shared__ int s[SCAN_B];
    int i = blockIdx.x * SCAN_B + threadIdx.x;
    s[threadIdx.x] = (i < NN) ? counts[i] : 0;
    __syncthreads();
    for (int off = 128; off > 0; off >>= 1) {
        if (threadIdx.x < off) s[threadIdx.x] += s[threadIdx.x + off];
        __syncthreads();
    }
    if (threadIdx.x == 0) bsum[blockIdx.x] = s[0];
}

__global__ void k_scan_top(int* __restrict__ bsum) {
    __shared__ int s[SCAN_B];
    int v = (threadIdx.x < SCAN_NB) ? bsum[threadIdx.x] : 0;
    s[threadIdx.x] = v;
    __syncthreads();
    for (int off = 1; off < SCAN_B; off <<= 1) {
        int t = (threadIdx.x >= off) ? s[threadIdx.x - off] : 0;
        __syncthreads();
        s[threadIdx.x] += t;
        __syncthreads();
    }
    if (threadIdx.x < SCAN_NB) bsum[threadIdx.x] = s[threadIdx.x] - v;
}

__global__ void k_scan_final(const int* __restrict__ counts, const int* __restrict__ bsum,
                             int* __restrict__ rowptr, int* __restrict__ fill) {
    __shared__ int s[SCAN_B];
    int i = blockIdx.x * SCAN_B + threadIdx.x;
    int v = (i < NN) ? counts[i] : 0;
    s[threadIdx.x] = v;
    __syncthreads();
    for (int off = 1; off < SCAN_B; off <<= 1) {
        int t = (threadIdx.x >= off) ? s[threadIdx.x - off] : 0;
        __syncthreads();
        s[threadIdx.x] += t;
        __syncthreads();
    }
    int excl = bsum[blockIdx.x] + s[threadIdx.x] - v;
    if (i < NN) { rowptr[i] = excl; fill[i] = excl; }
    if (i == NN - 1) rowptr[NN] = excl + v;
}

__global__ void k_scatter(const int* __restrict__ src2, const int* __restrict__ dst2,
                          int* __restrict__ fill, int* __restrict__ src_sorted) {
    int e = blockIdx.x * blockDim.x + threadIdx.x;
    if (e >= EE) return;
    int d = dst2[e];
    int p = atomicAdd(&fill[d], 1);
    src_sorted[p] = src2[e];
}

// ---------------- GEMM v1 (validated) for the N=40 head GEMM ----------------
#define GBM 128
#define GBN 64
#define GBK 16

__global__ __launch_bounds__(256) void k_gemm_tf32(
    const float* __restrict__ A, const float* __restrict__ B,
    float* __restrict__ C, int M, int N, int K,
    const float* __restrict__ bias, int do_relu)
{
    __shared__ float As[GBM][GBK + 4];
    __shared__ float Bs[GBK][GBN + 4];
    __shared__ float Cs[GBM][GBN];

    int tid = threadIdx.x;
    int warp = tid >> 5;
    int wm = warp >> 1;
    int wn = warp & 1;
    int row0 = blockIdx.y * GBM;
    int col0 = blockIdx.x * GBN;

    wmma::fragment<wmma::accumulator, 16, 16, 8, float> acc[2][2];
#pragma unroll
    for (int i = 0; i < 2; i++)
#pragma unroll
        for (int j = 0; j < 2; j++) wmma::fill_fragment(acc[i][j], 0.0f);

    for (int k0 = 0; k0 < K; k0 += GBK) {
#pragma unroll
        for (int t = 0; t < 2; t++) {
            int idx = tid + t * 256;
            int r = idx >> 2;
            int c4 = (idx & 3) * 4;
            float4 v = make_float4(0.f, 0.f, 0.f, 0.f);
            if (row0 + r < M)
                v = *(const float4*)(A + (size_t)(row0 + r) * K + k0 + c4);
            As[r][c4 + 0] = wmma::__float_to_tf32(v.x);
            As[r][c4 + 1] = wmma::__float_to_tf32(v.y);
            As[r][c4 + 2] = wmma::__float_to_tf32(v.z);
            As[r][c4 + 3] = wmma::__float_to_tf32(v.w);
        }
        {
            int r = tid >> 4;
            int c0 = (tid & 15) * 4;
#pragma unroll
            for (int j = 0; j < 4; j++) {
                int c = c0 + j;
                float v = 0.f;
                if (col0 + c < N) v = B[(size_t)(k0 + r) * N + col0 + c];
                Bs[r][c] = wmma::__float_to_tf32(v);
            }
        }
        __syncthreads();

#pragma unroll
        for (int kk = 0; kk < GBK; kk += 8) {
            wmma::fragment<wmma::matrix_a, 16, 16, 8, wmma::precision::tf32, wmma::row_major> a[2];
            wmma::fragment<wmma::matrix_b, 16, 16, 8, wmma::precision::tf32, wmma::row_major> b[2];
            wmma::load_matrix_sync(a[0], &As[wm * 32 +  0][kk], GBK + 4);
            wmma::load_matrix_sync(a[1], &As[wm * 32 + 16][kk], GBK + 4);
            wmma::load_matrix_sync(b[0], &Bs[kk][wn * 32 +  0], GBN + 4);
            wmma::load_matrix_sync(b[1], &Bs[kk][wn * 32 + 16], GBN + 4);
#pragma unroll
            for (int i = 0; i < 2; i++)
#pragma unroll
                for (int j = 0; j < 2; j++)
                    wmma::mma_sync(acc[i][j], a[i], b[j], acc[i][j]);
        }
        __syncthreads();
    }

#pragma unroll
    for (int i = 0; i < 2; i++)
#pragma unroll
        for (int j = 0; j < 2; j++)
            wmma::store_matrix_sync(&Cs[wm * 32 + i * 16][wn * 32 + j * 16],
                                    acc[i][j], GBN, wmma::mem_row_major);
    __syncthreads();

#pragma unroll
    for (int it = 0; it < 8; it++) {
        int idx = tid + it * 256;
        int r = idx >> 4;
        int c4 = (idx & 15) * 4;
        int gr = row0 + r;
        if (gr >= M) continue;
        float4 v = *(const float4*)&Cs[r][c4];
        int gc = col0 + c4;
        float* vv = &v.x;
        if (bias) {
#pragma unroll
            for (int j = 0; j < 4; j++)
                if (gc + j < N) vv[j] += bias[gc + j];
        }
        if (do_relu) {
#pragma unroll
            for (int j = 0; j < 4; j++) vv[j] = fmaxf(vv[j], 0.f);
        }
        if (gc + 4 <= N) {
            *(float4*)(C + (size_t)gr * N + gc) = v;
        } else {
#pragma unroll
            for (int j = 0; j < 4; j++)
                if (gc + j < N) C[(size_t)gr * N + gc + j] = vv[j];
        }
    }
}

// ---------------- bias+relu elementwise (Wm1 epilogue) ----------------------
__global__ void k_biasrelu(float* __restrict__ h, const float* __restrict__ bias) {
    int i = blockIdx.x * blockDim.x + threadIdx.x;
    if (i >= NN * 64) return;
    int c4 = (i & 63) * 4;
    float4 v = ((float4*)h)[i];
    const float4 b = *(const float4*)(bias + c4);
    v.x = fmaxf(v.x + b.x, 0.f); v.y = fmaxf(v.y + b.y, 0.f);
    v.z = fmaxf(v.z + b.z, 0.f); v.w = fmaxf(v.w + b.w, 0.f);
    ((float4*)h)[i] = v;
}

// ---------------- per-node attention logits (fp32 h) ------------------------
__global__ void k_logits(const float* __restrict__ h, const float* __restrict__ a_s,
                         const float* __restrict__ a_d,
                         float* __restrict__ srcl, float* __restrict__ dstl) {
    int warp = (blockIdx.x * blockDim.x + threadIdx.x) >> 5;
    int lane = threadIdx.x & 31;
    if (warp >= NN) return;
    int n = warp;
    const float4* hp = (const float4*)(h + (size_t)n * HW) + lane * 2;
    float4 v0 = hp[0], v1 = hp[1];
    int head = lane >> 3, sub = lane & 7;
    const float4* ap = (const float4*)(a_s + head * 64 + sub * 8);
    const float4* dp = (const float4*)(a_d + head * 64 + sub * 8);
    float4 s0 = ap[0], s1 = ap[1];
    float4 d0 = dp[0], d1 = dp[1];
    float ps = v0.x * s0.x + v0.y * s0.y + v0.z * s0.z + v0.w * s0.w
             + v1.x * s1.x + v1.y * s1.y + v1.z * s1.z + v1.w * s1.w;
    float pd = v0.x * d0.x + v0.y * d0.y + v0.z * d0.z + v0.w * d0.w
             + v1.x * d1.x + v1.y * d1.y + v1.z * d1.z + v1.w * d1.w;
#pragma unroll
    for (int off = 4; off >= 1; off >>= 1) {
        ps += __shfl_down_sync(0xffffffffu, ps, off, 8);
        pd += __shfl_down_sync(0xffffffffu, pd, off, 8);
    }
    if (sub == 0) {
        srcl[n * 4 + head] = ps;
        dstl[n * 4 + head] = pd;
    }
}

// ---------------- segment max ------------------------------------------------
__global__ void k_maxes(const float* __restrict__ srcl, const float* __restrict__ dstl,
                        const int* __restrict__ rowptr, const int* __restrict__ src_sorted,
                        float* __restrict__ amax) {
    int t = blockIdx.x * blockDim.x + threadIdx.x;
    if (t >= NN * 4) return;
    int n = t >> 2, hd = t & 3;
    float dl = dstl[t];
    int b = rowptr[n], e = rowptr[n + 1];
    float mx = -1e30f;
    for (int i = b; i < e; i++) {
        int s = src_sorted[i];
        float a = srcl[s * 4 + hd] + dl;
        a = a > 0.f ? a : 0.2f * a;
        mx = fmaxf(mx, a);
    }
    amax[t] = mx;
}

// ---------------- fused softmax-aggregate (bf16 h gathers) -------------------
__global__ void k_agg_fused(const __nv_bfloat16* __restrict__ hb,
                            const int* __restrict__ rowptr,
                            const int* __restrict__ src_sorted,
                            const float* __restrict__ srcl, const float* __restrict__ dstl,
                            const float* __restrict__ amax, const float* __restrict__ bias,
                            float* __restrict__ out) {
    int warp = (blockIdx.x * blockDim.x + threadIdx.x) >> 5;
    int lane = threadIdx.x & 31;
    if (warp >= NN) return;
    int n = warp;
    int head = lane >> 3;
    float am = amax[n * 4 + head];
    float dl = dstl[n * 4 + head];
    int b = rowptr[n], e = rowptr[n + 1];
    float den = 0.f;
    float acc[8] = {0.f, 0.f, 0.f, 0.f, 0.f, 0.f, 0.f, 0.f};
    for (int i = b; i < e; i++) {
        int s = src_sorted[i];
        float a = __ldg(&srcl[s * 4 + head]) + dl;
        a = a > 0.f ? a : 0.2f * a;
        float ev = __expf(a - am);
        den += ev;
        // lane's 8 channels as one 16B load of bf16
        uint4 u = *(const uint4*)(hb + (size_t)s * HW + lane * 8);
        float2 f0 = __bfloat1622float2(*(__nv_bfloat162*)&u.x);
        float2 f1 = __bfloat1622float2(*(__nv_bfloat162*)&u.y);
        float2 f2 = __bfloat1622float2(*(__nv_bfloat162*)&u.z);
        float2 f3 = __bfloat1622float2(*(__nv_bfloat162*)&u.w);
        acc[0] += f0.x * ev; acc[1] += f0.y * ev;
        acc[2] += f1.x * ev; acc[3] += f1.y * ev;
        acc[4] += f2.x * ev; acc[5] += f2.y * ev;
        acc[6] += f3.x * ev; acc[7] += f3.y * ev;
    }
    float rinv = 1.0f / den;
    const float* bp = bias + lane * 8;
    float o[8];
#pragma unroll
    for (int j = 0; j < 8; j++)
        o[j] = wmma::__float_to_tf32(fmaxf(acc[j] * rinv + bp[j], 0.f));
    float4* op = (float4*)(out + (size_t)n * HW) + lane * 2;
    op[0] = make_float4(o[0], o[1], o[2], o[3]);
    op[1] = make_float4(o[4], o[5], o[6], o[7]);
}

// ---------------- host launcher ----------------
extern "C" void kernel_launch(void* const* d_in, const int* in_sizes, int n_in,
                              void* d_out, int out_size) {
    const float* x   = (const float*)d_in[0];
    const void*  ei  = d_in[1];
    const float* W1  = (const float*)d_in[2];
    const float* as1 = (const float*)d_in[3];
    const float* ad1 = (const float*)d_in[4];
    const float* b1  = (const float*)d_in[5];
    const float* W2  = (const float*)d_in[6];
    const float* as2 = (const float*)d_in[7];
    const float* ad2 = (const float*)d_in[8];
    const float* b2  = (const float*)d_in[9];
    const float* W3  = (const float*)d_in[10];
    const float* as3 = (const float*)d_in[11];
    const float* ad3 = (const float*)d_in[12];
    const float* b3  = (const float*)d_in[13];
    const float* Wm1 = (const float*)d_in[14];
    const float* bm1 = (const float*)d_in[15];
    const float* Wm2 = (const float*)d_in[16];
    const float* bm2 = (const float*)d_in[17];
    float* out = (float*)d_out;

    float *p_h, *p_feat, *p_wr, *p_srcl, *p_dstl, *p_amax;
    __nv_bfloat16* p_hb;
    int *p_src2, *p_dst2, *p_srcs, *p_counts, *p_fill, *p_rowptr, *p_bsum;
    cudaGetSymbolAddress((void**)&p_h, g_h);
    cudaGetSymbolAddress((void**)&p_hb, g_hb);
    cudaGetSymbolAddress((void**)&p_feat, g_feat);
    cudaGetSymbolAddress((void**)&p_wr, g_wr);
    cudaGetSymbolAddress((void**)&p_srcl, g_srcl);
    cudaGetSymbolAddress((void**)&p_dstl, g_dstl);
    cudaGetSymbolAddress((void**)&p_amax, g_amax);
    cudaGetSymbolAddress((void**)&p_src2, g_src2);
    cudaGetSymbolAddress((void**)&p_dst2, g_dst2);
    cudaGetSymbolAddress((void**)&p_srcs, g_src_sorted);
    cudaGetSymbolAddress((void**)&p_counts, g_counts);
    cudaGetSymbolAddress((void**)&p_fill, g_fill);
    cudaGetSymbolAddress((void**)&p_rowptr, g_rowptr);
    cudaGetSymbolAddress((void**)&p_bsum, g_bsum);

    cudaFuncSetAttribute(k_gemm4, cudaFuncAttributeMaxDynamicSharedMemorySize, G4_SMEM);

    const int warpsGrid = (NN * 32 + 255) / 256;
    const int maxGrid   = (NN * 4 + 255) / 256;
    const int h2bGrid   = (NN * 64 + 255) / 256;
    dim3 bigGrid(HW / BGN, NNP / BGM);                   // (2, 391)
    dim3 outGrid(1, (NN + GBM - 1) / GBM);

    // slots 0..3: detect, round_w, round_x, GEMM1 (slot 3 = ncu capture window)
    k_detect<<<1, 512>>>(ei);                                              // 0
    k_round_w<<<(WTOT + 255) / 256, 256>>>(W1, W2, W3, Wm1);               // 1
    k_round_x<<<(NN * IN_FEAT + 255) / 256, 256>>>(x, p_feat);             // 2
    k_gemm4<<<bigGrid, 256, G4_SMEM>>>(p_feat, p_wr + W1OFF, p_h, NN, IN_FEAT); // 3

    // CSR build (independent of GEMM1)
    k_zero_counts<<<(NN + 255) / 256, 256>>>(p_counts, NN);
    k_build_edges<<<(EE + 255) / 256, 256>>>(ei, p_src2, p_dst2, p_counts);
    k_blocksum<<<SCAN_NB, SCAN_B>>>(p_counts, p_bsum);
    k_scan_top<<<1, SCAN_B>>>(p_bsum);
    k_scan_final<<<SCAN_NB, SCAN_B>>>(p_counts, p_bsum, p_rowptr, p_fill);
    k_scatter<<<(EE + 255) / 256, 256>>>(p_src2, p_dst2, p_fill, p_srcs);

    // --- GAT layer 1 rest ---
    k_h2b<<<h2bGrid, 256>>>(p_h, p_hb);
    k_logits<<<warpsGrid, 256>>>(p_h, as1, ad1, p_srcl, p_dstl);
    k_maxes<<<maxGrid, 256>>>(p_srcl, p_dstl, p_rowptr, p_srcs, p_amax);
    k_agg_fused<<<warpsGrid, 256>>>(p_hb, p_rowptr, p_srcs, p_srcl, p_dstl, p_amax, b1, p_feat);

    // --- GAT layer 2 ---
    k_gemm4<<<bigGrid, 256, G4_SMEM>>>(p_feat, p_wr + W2OFF, p_h, NN, HW);
    k_h2b<<<h2bGrid, 256>>>(p_h, p_hb);
    k_logits<<<warpsGrid, 256>>>(p_h, as2, ad2, p_srcl, p_dstl);
    k_maxes<<<maxGrid, 256>>>(p_srcl, p_dstl, p_rowptr, p_srcs, p_amax);
    k_agg_fused<<<warpsGrid, 256>>>(p_hb, p_rowptr, p_srcs, p_srcl, p_dstl, p_amax, b2, p_feat);

    // --- GAT layer 3 ---
    k_gemm4<<<bigGrid, 256, G4_SMEM>>>(p_feat, p_wr + W3OFF, p_h, NN, HW);
    k_h2b<<<h2bGrid, 256>>>(p_h, p_hb);
    k_logits<<<warpsGrid, 256>>>(p_h, as3, ad3, p_srcl, p_dstl);
    k_maxes<<<maxGrid, 256>>>(p_srcl, p_dstl, p_rowptr, p_srcs, p_amax);
    k_agg_fused<<<warpsGrid, 256>>>(p_hb, p_rowptr, p_srcs, p_srcl, p_dstl, p_amax, b3, p_feat);

    // --- MLP head ---
    k_gemm4<<<bigGrid, 256, G4_SMEM>>>(p_feat, p_wr + WM1OFF, p_h, NN, HW);
    k_biasrelu<<<(NN * 64 + 255) / 256, 256>>>(p_h, bm1);
    k_gemm_tf32<<<outGrid, 256>>>(p_h, Wm2, out, NN, OUTF, HW, bm2, 0);
}

// round 17
// speedup vs baseline: 1.5150x; 1.5150x over previous
#include <cuda_runtime.h>
#include <cuda_bf16.h>
#include <mma.h>
#include <cstdint>

using namespace nvcuda;

#define NN 50000
#define NNP 50048              // 391*128: padded rows for guard-free GEMM stores
#define NE 800000
#define EE (NE + NN)           // edges + self loops = 850000
#define HW 256
#define IN_FEAT 128
#define OUTF 40

// weight scratch offsets (tf32-rounded copies)
#define W1OFF 0
#define W2OFF 32768
#define W3OFF 98304
#define WM1OFF 163840
#define WTOT 229376

// ---------------- scratch ----------------
__device__ float g_h[NNP * HW];              // GEMM output (fp32)
__device__ __nv_bfloat16 g_hb[NN * HW];      // bf16 mirror of h for agg gathers
__device__ float g_feat[NN * HW];            // staged rounded x -> layer outputs
__device__ float g_wr[WTOT];                 // tf32-rounded weights
__device__ float g_srcl[NN * 4];
__device__ float g_dstl[NN * 4];
__device__ float g_amax[NN * 4];
__device__ int   g_src2[EE];
__device__ int   g_dst2[EE];
__device__ int   g_src_sorted[EE];
__device__ int   g_counts[NN];
__device__ int   g_fill[NN];
__device__ int   g_rowptr[NN + 1];
__device__ int   g_bsum[256];
__device__ int   g_is64;

// ---------------- cp.async helpers ----------------
__device__ __forceinline__ void cp16(void* dst_smem, const void* src) {
    uint32_t sa = (uint32_t)__cvta_generic_to_shared(dst_smem);
    asm volatile("cp.async.ca.shared.global [%0], [%1], 16;\n" :: "r"(sa), "l"(src));
}
__device__ __forceinline__ void cp_commit() {
    asm volatile("cp.async.commit_group;\n");
}
template <int N>
__device__ __forceinline__ void cp_wait() {
    asm volatile("cp.async.wait_group %0;\n" :: "n"(N));
}

// ---------------- dtype detection ----------------
__global__ void k_detect(const void* __restrict__ ei) {
    __shared__ int bad;
    if (threadIdx.x == 0) bad = 0;
    __syncthreads();
    const long long* p = (const long long*)ei;
    long long v = p[threadIdx.x];
    if (v < 0 || v >= (long long)NN) bad = 1;
    __syncthreads();
    if (threadIdx.x == 0) g_is64 = bad ? 0 : 1;
}

// ---------------- tf32 pre-rounding ----------------
__global__ void k_round_w(const float* __restrict__ W1, const float* __restrict__ W2,
                          const float* __restrict__ W3, const float* __restrict__ Wm1) {
    int i = blockIdx.x * blockDim.x + threadIdx.x;
    if (i >= WTOT) return;
    float v;
    if (i < W2OFF)       v = W1[i];
    else if (i < W3OFF)  v = W2[i - W2OFF];
    else if (i < WM1OFF) v = W3[i - W3OFF];
    else                 v = Wm1[i - WM1OFF];
    g_wr[i] = wmma::__float_to_tf32(v);
}

__global__ void k_round_x(const float* __restrict__ x, float* __restrict__ dst) {
    int i = blockIdx.x * blockDim.x + threadIdx.x;
    if (i >= NN * IN_FEAT) return;
    dst[i] = wmma::__float_to_tf32(x[i]);
}

// ---------------- GEMM v6: cp.async double-buffer + fused bf16 epilogue ----
// 256thr / 8 warps, warp tile 64x32 (4x2 frags), block 128x128, BK=32.
// Epilogue stages C through the (free) pipeline smem and emits fp32 + bf16.
#define BGM 128
#define BGN 128
#define BGK 32
#define PA 36
#define PB 132
#define ASZ (BGM * PA)
#define BSZ (BGK * PB)
#define G4_SMEM ((2 * ASZ + 2 * BSZ) * 4)   // 70656 bytes >= 64KB C staging

__global__ __launch_bounds__(256, 2) void k_gemm4(
    const float* __restrict__ A, const float* __restrict__ B,
    float* __restrict__ C, __nv_bfloat16* __restrict__ HB, int M, int K)
{
    extern __shared__ float smem[];
    float* As = smem;
    float* Bs = smem + 2 * ASZ;

    int tid = threadIdx.x;
    int warp = tid >> 5;
    int wm = warp >> 2;
    int wn = warp & 3;
    int row0 = blockIdx.y * BGM;
    int col0 = blockIdx.x * BGN;

    wmma::fragment<wmma::accumulator, 16, 16, 8, float> acc[4][2];
#pragma unroll
    for (int i = 0; i < 4; i++)
#pragma unroll
        for (int j = 0; j < 2; j++) wmma::fill_fragment(acc[i][j], 0.0f);

    const int T = K / BGK;

    auto issue = [&](int t, int buf) {
        int k0 = t * BGK;
        float* Ab = As + buf * ASZ;
        float* Bb = Bs + buf * BSZ;
#pragma unroll
        for (int i = 0; i < 4; i++) {
            int idx = tid + i * 256;
            int r = idx >> 3, c4 = (idx & 7) * 4;
            int gr = min(row0 + r, M - 1);          // clamp: pad rows never read
            cp16(Ab + r * PA + c4, A + (size_t)gr * K + k0 + c4);
        }
#pragma unroll
        for (int i = 0; i < 4; i++) {
            int idx = tid + i * 256;
            int r = idx >> 5, c4 = (idx & 31) * 4;
            cp16(Bb + r * PB + c4, B + (size_t)(k0 + r) * HW + col0 + c4);
        }
        cp_commit();
    };

    issue(0, 0);

    for (int t = 0; t < T; t++) {
        int buf = t & 1;
        if (t + 1 < T) { issue(t + 1, (t + 1) & 1); cp_wait<1>(); }
        else           { cp_wait<0>(); }
        __syncthreads();

        float* Ab = As + buf * ASZ;
        float* Bb = Bs + buf * BSZ;
#pragma unroll
        for (int kk = 0; kk < BGK; kk += 8) {
            wmma::fragment<wmma::matrix_a, 16, 16, 8, wmma::precision::tf32, wmma::row_major> a[4];
            wmma::fragment<wmma::matrix_b, 16, 16, 8, wmma::precision::tf32, wmma::row_major> b[2];
#pragma unroll
            for (int i = 0; i < 4; i++)
                wmma::load_matrix_sync(a[i], Ab + (wm * 64 + i * 16) * PA + kk, PA);
#pragma unroll
            for (int j = 0; j < 2; j++)
                wmma::load_matrix_sync(b[j], Bb + kk * PB + wn * 32 + j * 16, PB);
#pragma unroll
            for (int i = 0; i < 4; i++)
#pragma unroll
                for (int j = 0; j < 2; j++)
                    wmma::mma_sync(acc[i][j], a[i], b[j], acc[i][j]);
        }
        __syncthreads();
    }

    // fused epilogue: fragments -> smem C stage -> gmem fp32 (+ bf16 mirror)
    float* Cs = smem;   // 128x128 fp32 = 64KB, pipeline buffers are dead now
#pragma unroll
    for (int i = 0; i < 4; i++)
#pragma unroll
        for (int j = 0; j < 2; j++)
            wmma::store_matrix_sync(Cs + (wm * 64 + i * 16) * BGN + wn * 32 + j * 16,
                                    acc[i][j], BGN, wmma::mem_row_major);
    __syncthreads();

#pragma unroll
    for (int it = 0; it < 16; it++) {
        int idx = tid + it * 256;          // 4096 float4 slots
        int r = idx >> 5;                  // 0..127
        int c4 = (idx & 31) * 4;
        float4 v = *(const float4*)(Cs + r * BGN + c4);
        int gr = row0 + r;
        *(float4*)(C + (size_t)gr * HW + col0 + c4) = v;
        if (HB && gr < NN) {
            __nv_bfloat162 lo = __floats2bfloat162_rn(v.x, v.y);
            __nv_bfloat162 hi = __floats2bfloat162_rn(v.z, v.w);
            uint2 pk;
            pk.x = *(uint32_t*)&lo;
            pk.y = *(uint32_t*)&hi;
            *(uint2*)(HB + (size_t)gr * HW + col0 + c4) = pk;
        }
    }
}

// ---------------- CSR build ----------------
__global__ void k_zero_counts(int* counts, int n) {
    int i = blockIdx.x * blockDim.x + threadIdx.x;
    if (i < n) counts[i] = 0;
}

__global__ void k_build_edges(const void* __restrict__ ei,
                              int* __restrict__ src2, int* __restrict__ dst2,
                              int* __restrict__ counts) {
    int e = blockIdx.x * blockDim.x + threadIdx.x;
    if (e >= EE) return;
    int s, d;
    if (e < NE) {
        if (g_is64) {
            const long long* p = (const long long*)ei;
            s = (int)p[e]; d = (int)p[NE + e];
        } else {
            const int* p = (const int*)ei;
            s = p[e]; d = p[NE + e];
        }
        s = min(max(s, 0), NN - 1);
        d = min(max(d, 0), NN - 1);
    } else {
        s = d = e - NE;
    }
    src2[e] = s;
    dst2[e] = d;
    atomicAdd(&counts[d], 1);
}

#define SCAN_B 256
#define SCAN_NB ((NN + SCAN_B - 1) / SCAN_B)   // 196

__global__ void k_blocksum(const int* __restrict__ counts, int* __restrict__ bsum) {
    __shared__ int s[SCAN_B];
    int i = blockIdx.x * SCAN_B + threadIdx.x;
    s[threadIdx.x] = (i < NN) ? counts[i] : 0;
    __syncthreads();
    for (int off = 128; off > 0; off >>= 1) {
        if (threadIdx.x < off) s[threadIdx.x] += s[threadIdx.x + off];
        __syncthreads();
    }
    if (threadIdx.x == 0) bsum[blockIdx.x] = s[0];
}

__global__ void k_scan_top(int* __restrict__ bsum) {
    __shared__ int s[SCAN_B];
    int v = (threadIdx.x < SCAN_NB) ? bsum[threadIdx.x] : 0;
    s[threadIdx.x] = v;
    __syncthreads();
    for (int off = 1; off < SCAN_B; off <<= 1) {
        int t = (threadIdx.x >= off) ? s[threadIdx.x - off] : 0;
        __syncthreads();
        s[threadIdx.x] += t;
        __syncthreads();
    }
    if (threadIdx.x < SCAN_NB) bsum[threadIdx.x] = s[threadIdx.x] - v;
}

__global__ void k_scan_final(const int* __restrict__ counts, const int* __restrict__ bsum,
                             int* __restrict__ rowptr, int* __restrict__ fill) {
    __shared__ int s[SCAN_B];
    int i = blockIdx.x * SCAN_B + threadIdx.x;
    int v = (i < NN) ? counts[i] : 0;
    s[threadIdx.x] = v;
    __syncthreads();
    for (int off = 1; off < SCAN_B; off <<= 1) {
        int t = (threadIdx.x >= off) ? s[threadIdx.x - off] : 0;
        __syncthreads();
        s[threadIdx.x] += t;
        __syncthreads();
    }
    int excl = bsum[blockIdx.x] + s[threadIdx.x] - v;
    if (i < NN) { rowptr[i] = excl; fill[i] = excl; }
    if (i == NN - 1) rowptr[NN] = excl + v;
}

__global__ void k_scatter(const int* __restrict__ src2, const int* __restrict__ dst2,
                          int* __restrict__ fill, int* __restrict__ src_sorted) {
    int e = blockIdx.x * blockDim.x + threadIdx.x;
    if (e >= EE) return;
    int d = dst2[e];
    int p = atomicAdd(&fill[d], 1);
    src_sorted[p] = src2[e];
}

// ---------------- GEMM v1 (validated) for the N=40 head GEMM ----------------
#define GBM 128
#define GBN 64
#define GBK 16

__global__ __launch_bounds__(256) void k_gemm_tf32(
    const float* __restrict__ A, const float* __restrict__ B,
    float* __restrict__ C, int M, int N, int K,
    const float* __restrict__ bias, int do_relu)
{
    __shared__ float As[GBM][GBK + 4];
    __shared__ float Bs[GBK][GBN + 4];
    __shared__ float Cs[GBM][GBN];

    int tid = threadIdx.x;
    int warp = tid >> 5;
    int wm = warp >> 1;
    int wn = warp & 1;
    int row0 = blockIdx.y * GBM;
    int col0 = blockIdx.x * GBN;

    wmma::fragment<wmma::accumulator, 16, 16, 8, float> acc[2][2];
#pragma unroll
    for (int i = 0; i < 2; i++)
#pragma unroll
        for (int j = 0; j < 2; j++) wmma::fill_fragment(acc[i][j], 0.0f);

    for (int k0 = 0; k0 < K; k0 += GBK) {
#pragma unroll
        for (int t = 0; t < 2; t++) {
            int idx = tid + t * 256;
            int r = idx >> 2;
            int c4 = (idx & 3) * 4;
            float4 v = make_float4(0.f, 0.f, 0.f, 0.f);
            if (row0 + r < M)
                v = *(const float4*)(A + (size_t)(row0 + r) * K + k0 + c4);
            As[r][c4 + 0] = wmma::__float_to_tf32(v.x);
            As[r][c4 + 1] = wmma::__float_to_tf32(v.y);
            As[r][c4 + 2] = wmma::__float_to_tf32(v.z);
            As[r][c4 + 3] = wmma::__float_to_tf32(v.w);
        }
        {
            int r = tid >> 4;
            int c0 = (tid & 15) * 4;
#pragma unroll
            for (int j = 0; j < 4; j++) {
                int c = c0 + j;
                float v = 0.f;
                if (col0 + c < N) v = B[(size_t)(k0 + r) * N + col0 + c];
                Bs[r][c] = wmma::__float_to_tf32(v);
            }
        }
        __syncthreads();

#pragma unroll
        for (int kk = 0; kk < GBK; kk += 8) {
            wmma::fragment<wmma::matrix_a, 16, 16, 8, wmma::precision::tf32, wmma::row_major> a[2];
            wmma::fragment<wmma::matrix_b, 16, 16, 8, wmma::precision::tf32, wmma::row_major> b[2];
            wmma::load_matrix_sync(a[0], &As[wm * 32 +  0][kk], GBK + 4);
            wmma::load_matrix_sync(a[1], &As[wm * 32 + 16][kk], GBK + 4);
            wmma::load_matrix_sync(b[0], &Bs[kk][wn * 32 +  0], GBN + 4);
            wmma::load_matrix_sync(b[1], &Bs[kk][wn * 32 + 16], GBN + 4);
#pragma unroll
            for (int i = 0; i < 2; i++)
#pragma unroll
                for (int j = 0; j < 2; j++)
                    wmma::mma_sync(acc[i][j], a[i], b[j], acc[i][j]);
        }
        __syncthreads();
    }

#pragma unroll
    for (int i = 0; i < 2; i++)
#pragma unroll
        for (int j = 0; j < 2; j++)
            wmma::store_matrix_sync(&Cs[wm * 32 + i * 16][wn * 32 + j * 16],
                                    acc[i][j], GBN, wmma::mem_row_major);
    __syncthreads();

#pragma unroll
    for (int it = 0; it < 8; it++) {
        int idx = tid + it * 256;
        int r = idx >> 4;
        int c4 = (idx & 15) * 4;
        int gr = row0 + r;
        if (gr >= M) continue;
        float4 v = *(const float4*)&Cs[r][c4];
        int gc = col0 + c4;
        float* vv = &v.x;
        if (bias) {
#pragma unroll
            for (int j = 0; j < 4; j++)
                if (gc + j < N) vv[j] += bias[gc + j];
        }
        if (do_relu) {
#pragma unroll
            for (int j = 0; j < 4; j++) vv[j] = fmaxf(vv[j], 0.f);
        }
        if (gc + 4 <= N) {
            *(float4*)(C + (size_t)gr * N + gc) = v;
        } else {
#pragma unroll
            for (int j = 0; j < 4; j++)
                if (gc + j < N) C[(size_t)gr * N + gc + j] = vv[j];
        }
    }
}

// ---------------- bias+relu elementwise (Wm1 epilogue) ----------------------
__global__ void k_biasrelu(float* __restrict__ h, const float* __restrict__ bias) {
    int i = blockIdx.x * blockDim.x + threadIdx.x;
    if (i >= NN * 64) return;
    int c4 = (i & 63) * 4;
    float4 v = ((float4*)h)[i];
    const float4 b = *(const float4*)(bias + c4);
    v.x = fmaxf(v.x + b.x, 0.f); v.y = fmaxf(v.y + b.y, 0.f);
    v.z = fmaxf(v.z + b.z, 0.f); v.w = fmaxf(v.w + b.w, 0.f);
    ((float4*)h)[i] = v;
}

// ---------------- per-node attention logits (fp32 h) ------------------------
__global__ void k_logits(const float* __restrict__ h, const float* __restrict__ a_s,
                         const float* __restrict__ a_d,
                         float* __restrict__ srcl, float* __restrict__ dstl) {
    int warp = (blockIdx.x * blockDim.x + threadIdx.x) >> 5;
    int lane = threadIdx.x & 31;
    if (warp >= NN) return;
    int n = warp;
    const float4* hp = (const float4*)(h + (size_t)n * HW) + lane * 2;
    float4 v0 = hp[0], v1 = hp[1];
    int head = lane >> 3, sub = lane & 7;
    const float4* ap = (const float4*)(a_s + head * 64 + sub * 8);
    const float4* dp = (const float4*)(a_d + head * 64 + sub * 8);
    float4 s0 = ap[0], s1 = ap[1];
    float4 d0 = dp[0], d1 = dp[1];
    float ps = v0.x * s0.x + v0.y * s0.y + v0.z * s0.z + v0.w * s0.w
             + v1.x * s1.x + v1.y * s1.y + v1.z * s1.z + v1.w * s1.w;
    float pd = v0.x * d0.x + v0.y * d0.y + v0.z * d0.z + v0.w * d0.w
             + v1.x * d1.x + v1.y * d1.y + v1.z * d1.z + v1.w * d1.w;
#pragma unroll
    for (int off = 4; off >= 1; off >>= 1) {
        ps += __shfl_down_sync(0xffffffffu, ps, off, 8);
        pd += __shfl_down_sync(0xffffffffu, pd, off, 8);
    }
    if (sub == 0) {
        srcl[n * 4 + head] = ps;
        dstl[n * 4 + head] = pd;
    }
}

// ---------------- segment max ------------------------------------------------
__global__ void k_maxes(const float* __restrict__ srcl, const float* __restrict__ dstl,
                        const int* __restrict__ rowptr, const int* __restrict__ src_sorted,
                        float* __restrict__ amax) {
    int t = blockIdx.x * blockDim.x + threadIdx.x;
    if (t >= NN * 4) return;
    int n = t >> 2, hd = t & 3;
    float dl = dstl[t];
    int b = rowptr[n], e = rowptr[n + 1];
    float mx = -1e30f;
    for (int i = b; i < e; i++) {
        int s = src_sorted[i];
        float a = srcl[s * 4 + hd] + dl;
        a = a > 0.f ? a : 0.2f * a;
        mx = fmaxf(mx, a);
    }
    amax[t] = mx;
}

// ---------------- fused softmax-aggregate (bf16 h gathers) -------------------
__global__ void k_agg_fused(const __nv_bfloat16* __restrict__ hb,
                            const int* __restrict__ rowptr,
                            const int* __restrict__ src_sorted,
                            const float* __restrict__ srcl, const float* __restrict__ dstl,
                            const float* __restrict__ amax, const float* __restrict__ bias,
                            float* __restrict__ out) {
    int warp = (blockIdx.x * blockDim.x + threadIdx.x) >> 5;
    int lane = threadIdx.x & 31;
    if (warp >= NN) return;
    int n = warp;
    int head = lane >> 3;
    float am = amax[n * 4 + head];
    float dl = dstl[n * 4 + head];
    int b = rowptr[n], e = rowptr[n + 1];
    float den = 0.f;
    float acc[8] = {0.f, 0.f, 0.f, 0.f, 0.f, 0.f, 0.f, 0.f};
    for (int i = b; i < e; i++) {
        int s = src_sorted[i];
        float a = __ldg(&srcl[s * 4 + head]) + dl;
        a = a > 0.f ? a : 0.2f * a;
        float ev = __expf(a - am);
        den += ev;
        uint4 u = *(const uint4*)(hb + (size_t)s * HW + lane * 8);
        float2 f0 = __bfloat1622float2(*(__nv_bfloat162*)&u.x);
        float2 f1 = __bfloat1622float2(*(__nv_bfloat162*)&u.y);
        float2 f2 = __bfloat1622float2(*(__nv_bfloat162*)&u.z);
        float2 f3 = __bfloat1622float2(*(__nv_bfloat162*)&u.w);
        acc[0] += f0.x * ev; acc[1] += f0.y * ev;
        acc[2] += f1.x * ev; acc[3] += f1.y * ev;
        acc[4] += f2.x * ev; acc[5] += f2.y * ev;
        acc[6] += f3.x * ev; acc[7] += f3.y * ev;
    }
    float rinv = 1.0f / den;
    const float* bp = bias + lane * 8;
    float o[8];
#pragma unroll
    for (int j = 0; j < 8; j++)
        o[j] = wmma::__float_to_tf32(fmaxf(acc[j] * rinv + bp[j], 0.f));
    float4* op = (float4*)(out + (size_t)n * HW) + lane * 2;
    op[0] = make_float4(o[0], o[1], o[2], o[3]);
    op[1] = make_float4(o[4], o[5], o[6], o[7]);
}

// ---------------- host launcher ----------------
extern "C" void kernel_launch(void* const* d_in, const int* in_sizes, int n_in,
                              void* d_out, int out_size) {
    const float* x   = (const float*)d_in[0];
    const void*  ei  = d_in[1];
    const float* W1  = (const float*)d_in[2];
    const float* as1 = (const float*)d_in[3];
    const float* ad1 = (const float*)d_in[4];
    const float* b1  = (const float*)d_in[5];
    const float* W2  = (const float*)d_in[6];
    const float* as2 = (const float*)d_in[7];
    const float* ad2 = (const float*)d_in[8];
    const float* b2  = (const float*)d_in[9];
    const float* W3  = (const float*)d_in[10];
    const float* as3 = (const float*)d_in[11];
    const float* ad3 = (const float*)d_in[12];
    const float* b3  = (const float*)d_in[13];
    const float* Wm1 = (const float*)d_in[14];
    const float* bm1 = (const float*)d_in[15];
    const float* Wm2 = (const float*)d_in[16];
    const float* bm2 = (const float*)d_in[17];
    float* out = (float*)d_out;

    float *p_h, *p_feat, *p_wr, *p_srcl, *p_dstl, *p_amax;
    __nv_bfloat16* p_hb;
    int *p_src2, *p_dst2, *p_srcs, *p_counts, *p_fill, *p_rowptr, *p_bsum;
    cudaGetSymbolAddress((void**)&p_h, g_h);
    cudaGetSymbolAddress((void**)&p_hb, g_hb);
    cudaGetSymbolAddress((void**)&p_feat, g_feat);
    cudaGetSymbolAddress((void**)&p_wr, g_wr);
    cudaGetSymbolAddress((void**)&p_srcl, g_srcl);
    cudaGetSymbolAddress((void**)&p_dstl, g_dstl);
    cudaGetSymbolAddress((void**)&p_amax, g_amax);
    cudaGetSymbolAddress((void**)&p_src2, g_src2);
    cudaGetSymbolAddress((void**)&p_dst2, g_dst2);
    cudaGetSymbolAddress((void**)&p_srcs, g_src_sorted);
    cudaGetSymbolAddress((void**)&p_counts, g_counts);
    cudaGetSymbolAddress((void**)&p_fill, g_fill);
    cudaGetSymbolAddress((void**)&p_rowptr, g_rowptr);
    cudaGetSymbolAddress((void**)&p_bsum, g_bsum);

    cudaFuncSetAttribute(k_gemm4, cudaFuncAttributeMaxDynamicSharedMemorySize, G4_SMEM);

    const int warpsGrid = (NN * 32 + 255) / 256;
    const int maxGrid   = (NN * 4 + 255) / 256;
    dim3 bigGrid(HW / BGN, NNP / BGM);                   // (2, 391)
    dim3 outGrid(1, (NN + GBM - 1) / GBM);

    // slots 0..3: detect, round_w, round_x, GEMM1 (slot 3 = ncu capture window)
    k_detect<<<1, 512>>>(ei);                                              // 0
    k_round_w<<<(WTOT + 255) / 256, 256>>>(W1, W2, W3, Wm1);               // 1
    k_round_x<<<(NN * IN_FEAT + 255) / 256, 256>>>(x, p_feat);             // 2
    k_gemm4<<<bigGrid, 256, G4_SMEM>>>(p_feat, p_wr + W1OFF, p_h, p_hb, NN, IN_FEAT); // 3

    // CSR build (independent of GEMM1)
    k_zero_counts<<<(NN + 255) / 256, 256>>>(p_counts, NN);
    k_build_edges<<<(EE + 255) / 256, 256>>>(ei, p_src2, p_dst2, p_counts);
    k_blocksum<<<SCAN_NB, SCAN_B>>>(p_counts, p_bsum);
    k_scan_top<<<1, SCAN_B>>>(p_bsum);
    k_scan_final<<<SCAN_NB, SCAN_B>>>(p_counts, p_bsum, p_rowptr, p_fill);
    k_scatter<<<(EE + 255) / 256, 256>>>(p_src2, p_dst2, p_fill, p_srcs);

    // --- GAT layer 1 rest ---
    k_logits<<<warpsGrid, 256>>>(p_h, as1, ad1, p_srcl, p_dstl);
    k_maxes<<<maxGrid, 256>>>(p_srcl, p_dstl, p_rowptr, p_srcs, p_amax);
    k_agg_fused<<<warpsGrid, 256>>>(p_hb, p_rowptr, p_srcs, p_srcl, p_dstl, p_amax, b1, p_feat);

    // --- GAT layer 2 ---
    k_gemm4<<<bigGrid, 256, G4_SMEM>>>(p_feat, p_wr + W2OFF, p_h, p_hb, NN, HW);
    k_logits<<<warpsGrid, 256>>>(p_h, as2, ad2, p_srcl, p_dstl);
    k_maxes<<<maxGrid, 256>>>(p_srcl, p_dstl, p_rowptr, p_srcs, p_amax);
    k_agg_fused<<<warpsGrid, 256>>>(p_hb, p_rowptr, p_srcs, p_srcl, p_dstl, p_amax, b2, p_feat);

    // --- GAT layer 3 ---
    k_gemm4<<<bigGrid, 256, G4_SMEM>>>(p_feat, p_wr + W3OFF, p_h, p_hb, NN, HW);
    k_logits<<<warpsGrid, 256>>>(p_h, as3, ad3, p_srcl, p_dstl);
    k_maxes<<<maxGrid, 256>>>(p_srcl, p_dstl, p_rowptr, p_srcs, p_amax);
    k_agg_fused<<<warpsGrid, 256>>>(p_hb, p_rowptr, p_srcs, p_srcl, p_dstl, p_amax, b3, p_feat);

    // --- MLP head (no bf16 mirror needed) ---
    k_gemm4<<<bigGrid, 256, G4_SMEM>>>(p_feat, p_wr + WM1OFF, p_h, (__nv_bfloat16*)nullptr, NN, HW);
    k_biasrelu<<<(NN * 64 + 255) / 256, 256>>>(p_h, bm1);
    k_gemm_tf32<<<outGrid, 256>>>(p_h, Wm2, out, NN, OUTF, HW, bm2, 0);
}